// round 4
// baseline (speedup 1.0000x reference)
#include <cuda_runtime.h>
#include <math.h>

#define DDIM 2048
#define EDIM 64
#define T_TILE 64
#define MAX_AMB 16384
#define AMB_TH 1e-3f

typedef unsigned long long ull;

__device__ __forceinline__ ull pack2(float lo, float hi) {
    ull r;
    asm("mov.b64 %0, {%1,%2};" : "=l"(r) : "f"(lo), "f"(hi));
    return r;
}
__device__ __forceinline__ void fma2(ull &acc, ull a, ull b) {
    asm("fma.rn.f32x2 %0, %1, %2, %0;" : "+l"(acc) : "l"(a), "l"(b));
}
__device__ __forceinline__ float2 unpack2(ull v) {
    float lo, hi;
    asm("mov.b64 {%0,%1}, %2;" : "=f"(lo), "=f"(hi) : "l"(v));
    return make_float2(lo, hi);
}

// Scratch for ambiguous (near-tie) tokens needing fp64 arbitration.
__device__ int  g_amb_count;
__device__ int  g_amb_tok[MAX_AMB];
__device__ int4 g_amb_cand[MAX_AMB];

// GEMM smem (W pre-duplicated as (w,w) pairs, layout [i][d][c] with e = 4c+i,
// so a warp's 16 ecol lanes read 128B contiguous -> conflict-free) unioned with
// the epilogue noisy-logits buffer.
struct SmemG {
    ull wr[4 * 32 * 16];   // 16 KB
    ull wn[4 * 32 * 16];   // 16 KB
};
union SmemU {
    SmemG g;
    float nl[T_TILE * 72]; // 18.4 KB noisy logits, padded rows
};

__global__ void zero_amb_kernel() { g_amb_count = 0; }

__global__ __launch_bounds__(256, 2) void router_kernel(
    const float* __restrict__ X,
    const float* __restrict__ Wr,
    const float* __restrict__ br,
    const float* __restrict__ Wn,
    const float* __restrict__ bn,
    const float* __restrict__ noise,
    float* __restrict__ out_probs,
    float* __restrict__ out_idx,
    int write_idx)
{
    __shared__ SmemU su;
    __shared__ __align__(16) float s_x[32 * 72];  // [d][72 floats], token pairs ull-readable
    __shared__ float s_br[EDIM], s_bn[EDIM];
    __shared__ float s_p1[T_TILE], s_p2[T_TILE];
    __shared__ int   s_i1[T_TILE], s_i2[T_TILE];

    const int tid  = threadIdx.x;
    const int ecol = tid & 15;   // expert group: experts ecol*4 .. ecol*4+3
    const int trow = tid >> 4;   // token group:  tokens  trow*4 .. trow*4+3
    const int tokBase = blockIdx.x * T_TILE;

    if (tid < EDIM) { s_br[tid] = br[tid]; s_bn[tid] = bn[tid]; }

    ull aR0[4], aR1[4], aN0[4], aN1[4];
#pragma unroll
    for (int i = 0; i < 4; i++) { aR0[i] = 0ull; aR1[i] = 0ull; aN0[i] = 0ull; aN1[i] = 0ull; }

    for (int dBase = 0; dBase < DDIM; dBase += 32) {
        // ---- stage X tile: 64 tokens x 32 d  ->  s_x[d][tok] ----
#pragma unroll
        for (int j = 0; j < 2; j++) {
            int f   = tid + j * 256;
            int tok = f >> 3;
            int dq  = f & 7;
            float4 v = *reinterpret_cast<const float4*>(
                X + (size_t)(tokBase + tok) * DDIM + dBase + dq * 4);
            s_x[(dq * 4 + 0) * 72 + tok] = v.x;
            s_x[(dq * 4 + 1) * 72 + tok] = v.y;
            s_x[(dq * 4 + 2) * 72 + tok] = v.z;
            s_x[(dq * 4 + 3) * 72 + tok] = v.w;
        }
        // ---- stage W tiles (both matrices), duplicated (w,w) ----
#pragma unroll
        for (int j = 0; j < 2; j++) {
            int f  = tid + j * 256;
            int dd = f >> 4;
            int eq = f & 15;
            float4 v = *reinterpret_cast<const float4*>(
                Wr + (size_t)(dBase + dd) * EDIM + eq * 4);
            su.g.wr[0 * 512 + dd * 16 + eq] = pack2(v.x, v.x);
            su.g.wr[1 * 512 + dd * 16 + eq] = pack2(v.y, v.y);
            su.g.wr[2 * 512 + dd * 16 + eq] = pack2(v.z, v.z);
            su.g.wr[3 * 512 + dd * 16 + eq] = pack2(v.w, v.w);
            float4 w = *reinterpret_cast<const float4*>(
                Wn + (size_t)(dBase + dd) * EDIM + eq * 4);
            su.g.wn[0 * 512 + dd * 16 + eq] = pack2(w.x, w.x);
            su.g.wn[1 * 512 + dd * 16 + eq] = pack2(w.y, w.y);
            su.g.wn[2 * 512 + dd * 16 + eq] = pack2(w.z, w.z);
            su.g.wn[3 * 512 + dd * 16 + eq] = pack2(w.w, w.w);
        }
        __syncthreads();

        const ull* xs64 = reinterpret_cast<const ull*>(s_x); // 36 ull per d-row
#pragma unroll
        for (int dd = 0; dd < 32; ++dd) {
            ull xp0 = xs64[dd * 36 + trow * 2 + 0];  // tokens (4*trow+0, 4*trow+1)
            ull xp1 = xs64[dd * 36 + trow * 2 + 1];  // tokens (4*trow+2, 4*trow+3)
#pragma unroll
            for (int i = 0; i < 4; i++) {
                ull wri = su.g.wr[i * 512 + dd * 16 + ecol];
                ull wni = su.g.wn[i * 512 + dd * 16 + ecol];
                fma2(aR0[i], xp0, wri);
                fma2(aR1[i], xp1, wri);
                fma2(aN0[i], xp0, wni);
                fma2(aN1[i], xp1, wni);
            }
        }
        __syncthreads();
    }

    // ---- epilogue: noisy logits -> smem ----
#pragma unroll
    for (int tp = 0; tp < 2; ++tp) {
#pragma unroll
        for (int i = 0; i < 4; i++) {
            float2 rr = unpack2(tp ? aR1[i] : aR0[i]);
            float2 nn = unpack2(tp ? aN1[i] : aN0[i]);
#pragma unroll
            for (int h = 0; h < 2; ++h) {
                int t = trow * 4 + tp * 2 + h;
                int e = ecol * 4 + i;
                float lr = (h ? rr.y : rr.x) + s_br[e];
                float ln = (h ? nn.y : nn.x) + s_bn[e];
                float nz = noise[(size_t)(tokBase + t) * EDIM + e];
                // jax.nn.softplus(x) = max(x,0) + log1p(exp(-|x|))
                float sp = fmaxf(ln, 0.0f) + log1pf(expf(-fabsf(ln)));
                su.nl[t * 72 + e] = lr + nz * sp;
            }
        }
    }
    __syncthreads();

    // ---- top-4 scan + 2-way softmax, one thread per token ----
    if (tid < T_TILE) {
        float v1 = -INFINITY, v2 = -INFINITY, v3 = -INFINITY, v4 = -INFINITY;
        int i1 = 0, i2 = 0, i3 = 0, i4 = 0;
        for (int e = 0; e < EDIM; e++) {
            float v = su.nl[tid * 72 + e];
            if (v > v1)      { v4=v3; i4=i3; v3=v2; i3=i2; v2=v1; i2=i1; v1=v; i1=e; }
            else if (v > v2) { v4=v3; i4=i3; v3=v2; i3=i2; v2=v;  i2=e; }
            else if (v > v3) { v4=v3; i4=i3; v3=v;  i3=e; }
            else if (v > v4) { v4=v;  i4=e; }
        }
        float ed = expf(v2 - v1);
        float s  = 1.0f + ed;
        s_p1[tid] = 1.0f / s;
        s_p2[tid] = ed / s;
        s_i1[tid] = i1;
        s_i2[tid] = i2;
        if (write_idx) {
            out_idx[(size_t)(tokBase + tid) * 2 + 0] = (float)i1;
            out_idx[(size_t)(tokBase + tid) * 2 + 1] = (float)i2;
        }
        // near-tie at the 1|2 boundary (index order) or 2|3 boundary (set
        // membership) -> flag for exact fp64 arbitration
        if ((v1 - v2) < AMB_TH || (v2 - v3) < AMB_TH) {
            int slot = atomicAdd(&g_amb_count, 1);
            if (slot < MAX_AMB) {
                g_amb_tok[slot]  = tokBase + tid;
                g_amb_cand[slot] = make_int4(i1, i2, i3, i4);
            }
        }
    }
    __syncthreads();

    // ---- cooperative coalesced probs write (zeros + 2 scattered values) ----
#pragma unroll
    for (int k = 0; k < 4; k++) {
        int f   = tid + k * 256;
        int tok = f >> 4;
        int q   = f & 15;
        int i1 = s_i1[tok], i2 = s_i2[tok];
        float p1 = s_p1[tok], p2 = s_p2[tok];
        float v[4] = {0.0f, 0.0f, 0.0f, 0.0f};
        int b = q * 4;
        if (i1 >= b && i1 < b + 4) v[i1 - b] = p1;
        if (i2 >= b && i2 < b + 4) v[i2 - b] = p2;
        *reinterpret_cast<float4*>(out_probs + (size_t)(tokBase + tok) * EDIM + b) =
            make_float4(v[0], v[1], v[2], v[3]);
    }
}

// fp64 arbitration for near-tie tokens: recompute the 4 candidate experts'
// route/noise logits exactly, re-decide top-2 with jax's stable (lower index
// first) tie-break, and patch probs/indices.
__global__ __launch_bounds__(256) void refine_kernel(
    const float* __restrict__ X,
    const float* __restrict__ Wr,
    const float* __restrict__ br,
    const float* __restrict__ Wn,
    const float* __restrict__ bn,
    const float* __restrict__ noise,
    float* __restrict__ out_probs,
    float* __restrict__ out_idx,
    int write_idx)
{
    __shared__ double s_dot[8];
    int count = g_amb_count;
    if (count > MAX_AMB) count = MAX_AMB;
    const int lane = threadIdx.x & 31;
    const int warp = threadIdx.x >> 5;   // 8 warps: warps 0-3 route, 4-7 noise

    for (int idx = blockIdx.x; idx < count; idx += gridDim.x) {
        int tok = g_amb_tok[idx];
        int4 cd = g_amb_cand[idx];
        int cand[4] = {cd.x, cd.y, cd.z, cd.w};

        int c = cand[warp & 3];
        const float* W  = (warp < 4) ? Wr : Wn;
        const float* Xr = X + (size_t)tok * DDIM;
        double acc = 0.0;
        for (int d = lane; d < DDIM; d += 32)
            acc = fma((double)Xr[d], (double)W[(size_t)d * EDIM + c], acc);
#pragma unroll
        for (int off = 16; off; off >>= 1)
            acc += __shfl_down_sync(0xffffffffu, acc, off);
        if (lane == 0) s_dot[warp] = acc;
        __syncthreads();

        if (threadIdx.x == 0) {
            double nv[4];
#pragma unroll
            for (int k = 0; k < 4; k++) {
                double lg = s_dot[k]     + (double)br[cand[k]];
                double nl = s_dot[4 + k] + (double)bn[cand[k]];
                double sp = fmax(nl, 0.0) + log1p(exp(-fabs(nl)));
                nv[k] = lg + (double)noise[(size_t)tok * EDIM + cand[k]] * sp;
            }
            int b1 = 0;
            for (int k = 1; k < 4; k++)
                if (nv[k] > nv[b1] || (nv[k] == nv[b1] && cand[k] < cand[b1])) b1 = k;
            int b2 = -1;
            for (int k = 0; k < 4; k++) {
                if (k == b1) continue;
                if (b2 < 0 || nv[k] > nv[b2] || (nv[k] == nv[b2] && cand[k] < cand[b2])) b2 = k;
            }
            double e = exp(nv[b2] - nv[b1]);
            double s = 1.0 + e;
            float p1 = (float)(1.0 / s);
            float p2 = (float)(e / s);
#pragma unroll
            for (int k = 0; k < 4; k++) {
                float pv = (k == b1) ? p1 : ((k == b2) ? p2 : 0.0f);
                out_probs[(size_t)tok * EDIM + cand[k]] = pv;
            }
            if (write_idx) {
                out_idx[(size_t)tok * 2 + 0] = (float)cand[b1];
                out_idx[(size_t)tok * 2 + 1] = (float)cand[b2];
            }
        }
        __syncthreads();
    }
}

extern "C" void kernel_launch(void* const* d_in, const int* in_sizes, int n_in,
                              void* d_out, int out_size) {
    const float* X     = (const float*)d_in[0];   // mh_output [B,S,D]
    const float* Wr    = (const float*)d_in[1];   // W_route   [D,E]
    const float* br    = (const float*)d_in[2];   // b_route   [E]
    const float* Wn    = (const float*)d_in[3];   // W_noise   [D,E]
    const float* bn    = (const float*)d_in[4];   // b_noise   [E]
    const float* noise = (const float*)d_in[5];   // noise     [B,S,E]

    int T = in_sizes[0] / DDIM;                   // 16384 tokens
    float* out       = (float*)d_out;
    float* out_probs = out;                       // [T, E]
    float* out_idx   = out + (size_t)T * EDIM;    // [T, 2] as floats (if present)
    int write_idx = (out_size >= T * EDIM + T * 2) ? 1 : 0;

    zero_amb_kernel<<<1, 1>>>();
    router_kernel<<<T / T_TILE, 256>>>(X, Wr, br, Wn, bn, noise,
                                       out_probs, out_idx, write_idx);
    refine_kernel<<<64, 256>>>(X, Wr, br, Wn, bn, noise,
                               out_probs, out_idx, write_idx);
}

// round 5
// speedup vs baseline: 1.4405x; 1.4405x over previous
#include <cuda_runtime.h>
#include <math.h>

#define DDIM 2048
#define EDIM 64
#define T_TILE 64
#define AMB_TH 1e-3f

typedef unsigned long long ull;

__device__ __forceinline__ ull pack2(float lo, float hi) {
    ull r;
    asm("mov.b64 %0, {%1,%2};" : "=l"(r) : "f"(lo), "f"(hi));
    return r;
}
__device__ __forceinline__ void fma2(ull &acc, ull a, ull b) {
    asm("fma.rn.f32x2 %0, %1, %2, %0;" : "+l"(acc) : "l"(a), "l"(b));
}
__device__ __forceinline__ float2 unpack2(ull v) {
    float lo, hi;
    asm("mov.b64 {%0,%1}, %2;" : "=f"(lo), "=f"(hi) : "l"(v));
    return make_float2(lo, hi);
}

// ---- shared memory ----
// W tile: for expert group i (e = ecol*4 + i), wrn[i*512 + dd*16 + ecol] is a
// 16B pair { (wr,wr), (wn,wn) } -> one LDS.128 per expert per matrix-pair.
// nl (noisy logits, epilogue) unions with the W tile (compute is done by then).
union SmemU {
    ulonglong2 wrn[4 * 32 * 16];   // 32 KB
    float nl[T_TILE * 68];         // 17.4 KB
};

struct Smem {
    SmemU u;
    float x[32 * 68];              // [d][68 floats] transposed X tile (8.7 KB)
    float br[EDIM], bn[EDIM];
    float p1[T_TILE], p2[T_TILE];
    int   i1[T_TILE], i2[T_TILE];
    int   atok[T_TILE];            // ambiguous tokens (block-local idx)
    int4  acand[T_TILE];           // their top-4 candidates
    int   na;                      // ambiguous count
    double dot[8];                 // fp64 refine scratch
};

__global__ __launch_bounds__(128, 2) void router_kernel(
    const float* __restrict__ X,
    const float* __restrict__ Wr,
    const float* __restrict__ br,
    const float* __restrict__ Wn,
    const float* __restrict__ bn,
    const float* __restrict__ noise,
    float* __restrict__ out_probs,
    float* __restrict__ out_idx,
    int write_idx)
{
    __shared__ Smem sm;

    const int tid  = threadIdx.x;
    const int ecol = tid & 15;   // 16 expert groups x 4 experts (e = ecol*4+i)
    const int trow = tid >> 4;   // 8 token groups x 8 tokens
    const int lane = tid & 31;
    const int wid  = tid >> 5;   // 4 warps
    const int tokBase = blockIdx.x * T_TILE;

    if (tid < EDIM) { sm.br[tid] = br[tid]; sm.bn[tid] = bn[tid]; }
    if (tid == 0) sm.na = 0;

    ull aR[4][4], aN[4][4];      // [token pair p][expert i]
#pragma unroll
    for (int p = 0; p < 4; p++)
#pragma unroll
        for (int i = 0; i < 4; i++) { aR[p][i] = 0ull; aN[p][i] = 0ull; }

    // register prefetch buffers for the next tile
    float4 px[4], pwr[4], pwn[4];

    // ---- prefetch tile 0 ----
#pragma unroll
    for (int j = 0; j < 4; j++) {
        int f = tid + j * 128;
        { int tok = f >> 3, dq = f & 7;
          px[j] = *reinterpret_cast<const float4*>(
              X + (size_t)(tokBase + tok) * DDIM + dq * 4); }
        { int dd = f >> 4, eq = f & 15;
          pwr[j] = *reinterpret_cast<const float4*>(Wr + (size_t)dd * EDIM + eq * 4);
          pwn[j] = *reinterpret_cast<const float4*>(Wn + (size_t)dd * EDIM + eq * 4); }
    }

    for (int tile = 0; tile < DDIM / 32; ++tile) {
        __syncthreads();   // previous compute finished; smem reusable

        // ---- store staged tile to smem ----
#pragma unroll
        for (int j = 0; j < 4; j++) {
            int f = tid + j * 128;
            { int tok = f >> 3, dq = f & 7;
              sm.x[(dq * 4 + 0) * 68 + tok] = px[j].x;
              sm.x[(dq * 4 + 1) * 68 + tok] = px[j].y;
              sm.x[(dq * 4 + 2) * 68 + tok] = px[j].z;
              sm.x[(dq * 4 + 3) * 68 + tok] = px[j].w; }
            { int dd = f >> 4, eq = f & 15;
              float vr[4] = {pwr[j].x, pwr[j].y, pwr[j].z, pwr[j].w};
              float vn[4] = {pwn[j].x, pwn[j].y, pwn[j].z, pwn[j].w};
#pragma unroll
              for (int i = 0; i < 4; i++) {
                  ulonglong2 wp;
                  wp.x = pack2(vr[i], vr[i]);
                  wp.y = pack2(vn[i], vn[i]);
                  sm.u.wrn[i * 512 + dd * 16 + eq] = wp;
              } }
        }
        __syncthreads();

        // ---- prefetch next tile (overlaps compute below) ----
        if (tile + 1 < DDIM / 32) {
            int dBase = (tile + 1) * 32;
#pragma unroll
            for (int j = 0; j < 4; j++) {
                int f = tid + j * 128;
                { int tok = f >> 3, dq = f & 7;
                  px[j] = *reinterpret_cast<const float4*>(
                      X + (size_t)(tokBase + tok) * DDIM + dBase + dq * 4); }
                { int dd = f >> 4, eq = f & 15;
                  pwr[j] = *reinterpret_cast<const float4*>(
                      Wr + (size_t)(dBase + dd) * EDIM + eq * 4);
                  pwn[j] = *reinterpret_cast<const float4*>(
                      Wn + (size_t)(dBase + dd) * EDIM + eq * 4); }
            }
        }

        // ---- compute: 32 d-steps, 32 FFMA2 + 6 LDS.128 each ----
        const ull* xs64 = reinterpret_cast<const ull*>(sm.x);   // 34 ull per d-row
#pragma unroll 8
        for (int dd = 0; dd < 32; ++dd) {
            const ulonglong2* xv = reinterpret_cast<const ulonglong2*>(
                xs64 + dd * 34 + trow * 4);
            ulonglong2 x01 = xv[0];
            ulonglong2 x23 = xv[1];
            ull xp[4] = {x01.x, x01.y, x23.x, x23.y};
#pragma unroll
            for (int i = 0; i < 4; i++) {
                ulonglong2 w = sm.u.wrn[i * 512 + dd * 16 + ecol];
#pragma unroll
                for (int p = 0; p < 4; p++) {
                    fma2(aR[p][i], xp[p], w.x);
                    fma2(aN[p][i], xp[p], w.y);
                }
            }
        }
    }
    __syncthreads();   // all compute done before nl overwrites the W union

    // ---- epilogue: noisy logits -> smem ----
#pragma unroll
    for (int p = 0; p < 4; ++p) {
#pragma unroll
        for (int h = 0; h < 2; ++h) {
            int t = trow * 8 + 2 * p + h;
            float4 nz4 = *reinterpret_cast<const float4*>(
                noise + (size_t)(tokBase + t) * EDIM + ecol * 4);
            float nzv[4] = {nz4.x, nz4.y, nz4.z, nz4.w};
#pragma unroll
            for (int i = 0; i < 4; i++) {
                int e = ecol * 4 + i;
                float2 rr = unpack2(aR[p][i]);
                float2 nn = unpack2(aN[p][i]);
                float lr = (h ? rr.y : rr.x) + sm.br[e];
                float ln = (h ? nn.y : nn.x) + sm.bn[e];
                // jax.nn.softplus(x) = max(x,0) + log1p(exp(-|x|))
                float sp = fmaxf(ln, 0.0f) + log1pf(expf(-fabsf(ln)));
                sm.u.nl[t * 68 + e] = lr + nzv[i] * sp;
            }
        }
    }
    __syncthreads();

    // ---- top-4 scan + 2-way softmax, one thread per token ----
    if (tid < T_TILE) {
        float v1 = -INFINITY, v2 = -INFINITY, v3 = -INFINITY, v4 = -INFINITY;
        int i1 = 0, i2 = 0, i3 = 0, i4 = 0;
        for (int e = 0; e < EDIM; e++) {
            float v = sm.u.nl[tid * 68 + e];
            if (v > v1)      { v4=v3; i4=i3; v3=v2; i3=i2; v2=v1; i2=i1; v1=v; i1=e; }
            else if (v > v2) { v4=v3; i4=i3; v3=v2; i3=i2; v2=v;  i2=e; }
            else if (v > v3) { v4=v3; i4=i3; v3=v;  i3=e; }
            else if (v > v4) { v4=v;  i4=e; }
        }
        float ed = expf(v2 - v1);
        float s  = 1.0f + ed;
        sm.p1[tid] = 1.0f / s;
        sm.p2[tid] = ed / s;
        sm.i1[tid] = i1;
        sm.i2[tid] = i2;
        if (write_idx) {
            out_idx[(size_t)(tokBase + tid) * 2 + 0] = (float)i1;
            out_idx[(size_t)(tokBase + tid) * 2 + 1] = (float)i2;
        }
        // near-tie at 1|2 (index order) or 2|3 (set membership) boundary
        if ((v1 - v2) < AMB_TH || (v2 - v3) < AMB_TH) {
            int slot = atomicAdd(&sm.na, 1);
            sm.atok[slot]  = tid;
            sm.acand[slot] = make_int4(i1, i2, i3, i4);
        }
    }
    __syncthreads();

    // ---- cooperative coalesced probs write (zeros + 2 scattered values) ----
#pragma unroll
    for (int k = 0; k < 8; k++) {
        int f   = tid + k * 128;
        int tok = f >> 4;
        int q   = f & 15;
        int i1 = sm.i1[tok], i2 = sm.i2[tok];
        float p1 = sm.p1[tok], p2 = sm.p2[tok];
        float v[4] = {0.0f, 0.0f, 0.0f, 0.0f};
        int b = q * 4;
        if (i1 >= b && i1 < b + 4) v[i1 - b] = p1;
        if (i2 >= b && i2 < b + 4) v[i2 - b] = p2;
        *reinterpret_cast<float4*>(out_probs + (size_t)(tokBase + tok) * EDIM + b) =
            make_float4(v[0], v[1], v[2], v[3]);
    }
    __syncthreads();   // probs fully written before refine patches

    // ---- in-block fp64 arbitration for near-tie tokens (rare) ----
    int na = sm.na;
    for (int a = 0; a < na; a++) {
        int tok = tokBase + sm.atok[a];
        int4 cd = sm.acand[a];
        int cand[4] = {cd.x, cd.y, cd.z, cd.w};

        // warp w: route+noise dots for candidate w
        int c = cand[wid];
        const float* Xr = X + (size_t)tok * DDIM;
        double accR = 0.0, accN = 0.0;
        for (int d = lane; d < DDIM; d += 32) {
            double xv = (double)Xr[d];
            accR = fma(xv, (double)Wr[(size_t)d * EDIM + c], accR);
            accN = fma(xv, (double)Wn[(size_t)d * EDIM + c], accN);
        }
#pragma unroll
        for (int off = 16; off; off >>= 1) {
            accR += __shfl_down_sync(0xffffffffu, accR, off);
            accN += __shfl_down_sync(0xffffffffu, accN, off);
        }
        if (lane == 0) { sm.dot[wid] = accR; sm.dot[4 + wid] = accN; }
        __syncthreads();

        if (tid == 0) {
            double nv[4];
#pragma unroll
            for (int k = 0; k < 4; k++) {
                double lg = sm.dot[k]     + (double)br[cand[k]];
                double nl = sm.dot[4 + k] + (double)bn[cand[k]];
                double sp = fmax(nl, 0.0) + log1p(exp(-fabs(nl)));
                nv[k] = lg + (double)noise[(size_t)tok * EDIM + cand[k]] * sp;
            }
            int b1 = 0;
            for (int k = 1; k < 4; k++)
                if (nv[k] > nv[b1] || (nv[k] == nv[b1] && cand[k] < cand[b1])) b1 = k;
            int b2 = -1;
            for (int k = 0; k < 4; k++) {
                if (k == b1) continue;
                if (b2 < 0 || nv[k] > nv[b2] || (nv[k] == nv[b2] && cand[k] < cand[b2])) b2 = k;
            }
            double e = exp(nv[b2] - nv[b1]);
            double s = 1.0 + e;
            float p1 = (float)(1.0 / s);
            float p2 = (float)(e / s);
#pragma unroll
            for (int k = 0; k < 4; k++) {
                float pv = (k == b1) ? p1 : ((k == b2) ? p2 : 0.0f);
                out_probs[(size_t)tok * EDIM + cand[k]] = pv;
            }
            if (write_idx) {
                out_idx[(size_t)tok * 2 + 0] = (float)cand[b1];
                out_idx[(size_t)tok * 2 + 1] = (float)cand[b2];
            }
        }
        __syncthreads();
    }
}

extern "C" void kernel_launch(void* const* d_in, const int* in_sizes, int n_in,
                              void* d_out, int out_size) {
    const float* X     = (const float*)d_in[0];   // mh_output [B,S,D]
    const float* Wr    = (const float*)d_in[1];   // W_route   [D,E]
    const float* br    = (const float*)d_in[2];   // b_route   [E]
    const float* Wn    = (const float*)d_in[3];   // W_noise   [D,E]
    const float* bn    = (const float*)d_in[4];   // b_noise   [E]
    const float* noise = (const float*)d_in[5];   // noise     [B,S,E]

    int T = in_sizes[0] / DDIM;                   // 16384 tokens
    float* out       = (float*)d_out;
    float* out_probs = out;                       // [T, E]
    float* out_idx   = out + (size_t)T * EDIM;    // [T, 2] as floats (if present)
    int write_idx = (out_size >= T * EDIM + T * 2) ? 1 : 0;

    router_kernel<<<T / T_TILE, 128>>>(X, Wr, br, Wn, bn, noise,
                                       out_probs, out_idx, write_idx);
}